// round 4
// baseline (speedup 1.0000x reference)
#include <cuda_runtime.h>

// ---- problem constants -----------------------------------------------------
#define BGRAPH 64
#define N_PER  2048
#define FDIM   64
#define NE     1048576
#define NNODE  (BGRAPH * N_PER)      // 131072
#define KSEL   1639                   // ceil(0.8*2048)
#define PSEL   (BGRAPH * KSEL)        // 104896
#define K0     209715                 // ascending rank of threshold: E-1 - int(0.8*(E-1))

// ---- output layout (float32, concatenated in return order) -----------------
#define OFF_X      0
#define OFF_EIDX   6713344            // PSEL*FDIM
#define OFF_EATTR  8810496            // + 2*NE
#define OFF_BATCH  17199104           // + 8*NE
#define OFF_SEL    17304000           // + PSEL

// ---- device scratch (no allocation allowed) --------------------------------
__device__ float        g_S[NE];
__device__ int          g_new_idx[NNODE];
__device__ int          g_perm[PSEL];
__device__ unsigned int g_hist1[65536];
__device__ unsigned int g_hist2[65536];
__device__ unsigned int g_sel_hi;
__device__ unsigned int g_rem;
__device__ float        g_th;

// ---- per-graph top-k via bitonic sort of packed (desc score, asc idx) keys -
// Also zeroes both radix histograms (64 blocks x 1024 threads = 65536 entries)
// so graph replays are deterministic.
__global__ void topk_kernel(const float* __restrict__ score, float* __restrict__ out) {
    __shared__ unsigned long long keys[N_PER];
    const int b = blockIdx.x;
    const int t = threadIdx.x;           // 1024 threads

    {   // zero histograms: global thread id covers [0, 65536)
        int h = b * 1024 + t;
        g_hist1[h] = 0u;
        g_hist2[h] = 0u;
    }

    for (int i = t; i < N_PER; i += 1024) {
        float s = score[b * N_PER + i];
        unsigned int bits = __float_as_uint(s);
        // monotone map: float -> ascending uint
        bits = (bits & 0x80000000u) ? ~bits : (bits | 0x80000000u);
        unsigned int dk = ~bits;         // descending order key
        keys[i] = (((unsigned long long)dk) << 32) | (unsigned int)i;
        g_new_idx[b * N_PER + i] = -1;   // init mask for this graph
    }
    __syncthreads();

    // bitonic sort ascending on u64 => descending score, lower index first on ties
    for (int k = 2; k <= N_PER; k <<= 1) {
        for (int j = k >> 1; j > 0; j >>= 1) {
            for (int i = t; i < N_PER; i += 1024) {
                int ixj = i ^ j;
                if (ixj > i) {
                    unsigned long long a = keys[i], c = keys[ixj];
                    bool up = ((i & k) == 0);
                    if ((a > c) == up) { keys[i] = c; keys[ixj] = a; }
                }
            }
            __syncthreads();
        }
    }

    for (int i = t; i < KSEL; i += 1024) {
        int idx  = (int)(keys[i] & 0xffffffffu);
        int node = b * N_PER + idx;
        int newp = b * KSEL + i;
        g_new_idx[node] = newp;
        g_perm[newp]    = node;
        out[OFF_BATCH + newp] = (float)b;
    }
}

// ---- x_out gather: one float4 per thread -----------------------------------
__global__ void gather_x_kernel(const float* __restrict__ x, float* __restrict__ out) {
    int tid = blockIdx.x * blockDim.x + threadIdx.x;   // PSEL*16 threads
    if (tid >= PSEL * 16) return;
    int row = tid >> 4, c = tid & 15;
    int node = g_perm[row];
    float4 v = ((const float4*)x)[(size_t)node * 16 + c];
    ((float4*)(out + OFF_X))[(size_t)row * 16 + c] = v;
}

// ---- edge kernel: 8 threads per edge ---------------------------------------
// Computes S=exp(||x_r - x_c||), hist1 of top-16 bits, edge remap + attr copy.
__global__ void edge_kernel(const int* __restrict__ ei,
                            const float* __restrict__ x,
                            const float* __restrict__ eattr,
                            float* __restrict__ out) {
    int g = blockIdx.x * blockDim.x + threadIdx.x;
    int e = g >> 3, lane8 = g & 7;
    if (e >= NE) return;

    int r = ei[e], c = ei[NE + e];

    const float4* xr = (const float4*)(x + (size_t)r * FDIM);
    const float4* xc = (const float4*)(x + (size_t)c * FDIM);
    float acc = 0.0f;
#pragma unroll
    for (int j = lane8; j < 16; j += 8) {
        float4 a = xr[j], bq = xc[j];
        float dx = a.x - bq.x, dy = a.y - bq.y, dz = a.z - bq.z, dw = a.w - bq.w;
        acc += dx * dx + dy * dy + dz * dz + dw * dw;
    }
#pragma unroll
    for (int o = 4; o > 0; o >>= 1) acc += __shfl_down_sync(0xffffffffu, acc, o, 8);

    bool valid = false;
    int nr = -1, nc = -1;
    if (lane8 < 2) {                       // only consuming lanes gather new ids
        nr = g_new_idx[r];
        nc = g_new_idx[c];
        valid = (nr >= 0) && (nc >= 0);
    }

    if (lane8 == 0) {
        float S = expf(acc > 0.0f ? sqrtf(acc) : 0.0f);   // _safe_norm semantics
        g_S[e] = S;
        atomicAdd(&g_hist1[__float_as_uint(S) >> 16], 1u);
        out[OFF_EIDX + e]      = (float)(valid ? nr : -1);
        out[OFF_EIDX + NE + e] = (float)(valid ? nc : -1);
    }
    if (lane8 < 2) {
        float4 a = valid ? ((const float4*)eattr)[(size_t)e * 2 + lane8]
                         : make_float4(0.f, 0.f, 0.f, 0.f);
        ((float4*)(out + OFF_EATTR))[(size_t)e * 2 + lane8] = a;
    }
}

// ---- scan 1: find high-16 bucket containing ascending rank K0 --------------
__global__ void scan1_kernel() {
    __shared__ unsigned part[1024];
    __shared__ unsigned pre[1024];
    int t = threadIdx.x;
    unsigned local = 0;
#pragma unroll 8
    for (int i = 0; i < 64; i++) local += g_hist1[t * 64 + i];
    part[t] = local;
    __syncthreads();
    if (t == 0) {
        unsigned s = 0;
        for (int i = 0; i < 1024; i++) { pre[i] = s; s += part[i]; }
    }
    __syncthreads();
    unsigned k = K0;
    if (k >= pre[t] && k < pre[t] + part[t]) {
        unsigned rem = k - pre[t], cum = 0;
        for (int i = 0; i < 64; i++) {
            unsigned h = g_hist1[t * 64 + i];
            if (rem < cum + h) { g_sel_hi = (unsigned)(t * 64 + i); g_rem = rem - cum; break; }
            cum += h;
        }
    }
}

// ---- histogram of low-16 bits within the selected high-16 bucket -----------
__global__ void hist2_kernel() {
    int e = blockIdx.x * blockDim.x + threadIdx.x;
    if (e >= NE) return;
    unsigned b = __float_as_uint(g_S[e]);
    if ((b >> 16) == g_sel_hi) atomicAdd(&g_hist2[b & 0xffffu], 1u);
}

// ---- scan 2: resolve exact threshold bits ----------------------------------
__global__ void scan2_kernel() {
    __shared__ unsigned part[1024];
    __shared__ unsigned pre[1024];
    int t = threadIdx.x;
    unsigned local = 0;
#pragma unroll 8
    for (int i = 0; i < 64; i++) local += g_hist2[t * 64 + i];
    part[t] = local;
    __syncthreads();
    if (t == 0) {
        unsigned s = 0;
        for (int i = 0; i < 1024; i++) { pre[i] = s; s += part[i]; }
    }
    __syncthreads();
    unsigned k = g_rem;
    if (k >= pre[t] && k < pre[t] + part[t]) {
        unsigned rem = k - pre[t], cum = 0;
        for (int i = 0; i < 64; i++) {
            unsigned h = g_hist2[t * 64 + i];
            if (rem < cum + h) {
                g_th = __uint_as_float((g_sel_hi << 16) | (unsigned)(t * 64 + i));
                break;
            }
            cum += h;
        }
    }
}

// ---- final select mask -----------------------------------------------------
__global__ void select_kernel(float* __restrict__ out) {
    int e = blockIdx.x * blockDim.x + threadIdx.x;
    if (e >= NE) return;
    out[OFF_SEL + e] = (g_S[e] > g_th) ? 1.0f : 0.0f;
}

extern "C" void kernel_launch(void* const* d_in, const int* in_sizes, int n_in,
                              void* d_out, int out_size) {
    const float* x     = (const float*)d_in[0];
    const float* score = (const float*)d_in[1];
    const int*   ei    = (const int*)d_in[2];
    const float* eattr = (const float*)d_in[3];
    float* out = (float*)d_out;

    topk_kernel<<<BGRAPH, 1024>>>(score, out);
    gather_x_kernel<<<(PSEL * 16 + 255) / 256, 256>>>(x, out);
    edge_kernel<<<(NE * 8) / 256, 256>>>(ei, x, eattr, out);
    scan1_kernel<<<1, 1024>>>();
    hist2_kernel<<<NE / 256, 256>>>();
    scan2_kernel<<<1, 1024>>>();
    select_kernel<<<NE / 256, 256>>>(out);
}

// round 9
// speedup vs baseline: 1.3673x; 1.3673x over previous
#include <cuda_runtime.h>

// ---- problem constants -----------------------------------------------------
#define BGRAPH 64
#define N_PER  2048
#define FDIM   64
#define NE     1048576
#define NNODE  (BGRAPH * N_PER)      // 131072
#define KSEL   1639                   // ceil(0.8*2048)
#define PSEL   (BGRAPH * KSEL)        // 104896
#define K0     209715                 // ascending rank of threshold: E-1 - int(0.8*(E-1))

// ---- output layout (float32, concatenated in return order) -----------------
#define OFF_X      0
#define OFF_EIDX   6713344            // PSEL*FDIM
#define OFF_EATTR  8810496            // + 2*NE
#define OFF_BATCH  17199104           // + 8*NE
#define OFF_SEL    17304000           // + PSEL

// ---- device scratch (no allocation allowed) --------------------------------
__device__ float        g_S[NE];
__device__ int          g_new_idx[NNODE];
__device__ int          g_perm[PSEL];
__device__ unsigned int g_hist1[65536];
__device__ unsigned int g_hist2[65536];
__device__ unsigned int g_sel_hi;
__device__ unsigned int g_rem;
__device__ float        g_th;

// ---- per-graph top-k via bitonic sort of packed (desc score, asc idx) keys -
// Also zeroes both radix histograms (64 blocks x 1024 threads = 65536 entries)
// so graph replays are deterministic.
__global__ void topk_kernel(const float* __restrict__ score, float* __restrict__ out) {
    __shared__ unsigned long long keys[N_PER];
    const int b = blockIdx.x;
    const int t = threadIdx.x;           // 1024 threads

    {   // zero histograms: global thread id covers [0, 65536)
        int h = b * 1024 + t;
        g_hist1[h] = 0u;
        g_hist2[h] = 0u;
    }

    for (int i = t; i < N_PER; i += 1024) {
        float s = score[b * N_PER + i];
        unsigned int bits = __float_as_uint(s);
        bits = (bits & 0x80000000u) ? ~bits : (bits | 0x80000000u);  // float->asc uint
        unsigned int dk = ~bits;                                      // descending key
        keys[i] = (((unsigned long long)dk) << 32) | (unsigned int)i;
        g_new_idx[b * N_PER + i] = -1;
    }
    __syncthreads();

    // bitonic sort ascending on u64 => descending score, lower index first on ties
    for (int k = 2; k <= N_PER; k <<= 1) {
        for (int j = k >> 1; j > 0; j >>= 1) {
            for (int i = t; i < N_PER; i += 1024) {
                int ixj = i ^ j;
                if (ixj > i) {
                    unsigned long long a = keys[i], c = keys[ixj];
                    bool up = ((i & k) == 0);
                    if ((a > c) == up) { keys[i] = c; keys[ixj] = a; }
                }
            }
            __syncthreads();
        }
    }

    for (int i = t; i < KSEL; i += 1024) {
        int idx  = (int)(keys[i] & 0xffffffffu);
        int node = b * N_PER + idx;
        int newp = b * KSEL + i;
        g_new_idx[node] = newp;
        g_perm[newp]    = node;
        out[OFF_BATCH + newp] = (float)b;
    }
}

// ---- x_out gather: one float4 per thread -----------------------------------
__global__ void gather_x_kernel(const float* __restrict__ x, float* __restrict__ out) {
    int tid = blockIdx.x * blockDim.x + threadIdx.x;   // PSEL*16 threads
    if (tid >= PSEL * 16) return;
    int row = tid >> 4, c = tid & 15;
    int node = g_perm[row];
    float4 v = ((const float4*)x)[(size_t)node * 16 + c];
    ((float4*)(out + OFF_X))[(size_t)row * 16 + c] = v;
}

// ---- edge kernel: 8 threads per edge ---------------------------------------
__global__ void edge_kernel(const int* __restrict__ ei,
                            const float* __restrict__ x,
                            const float* __restrict__ eattr,
                            float* __restrict__ out) {
    int g = blockIdx.x * blockDim.x + threadIdx.x;
    int e = g >> 3, lane8 = g & 7;
    if (e >= NE) return;

    int r = ei[e], c = ei[NE + e];

    const float4* xr = (const float4*)(x + (size_t)r * FDIM);
    const float4* xc = (const float4*)(x + (size_t)c * FDIM);
    float acc = 0.0f;
#pragma unroll
    for (int j = lane8; j < 16; j += 8) {
        float4 a = xr[j], bq = xc[j];
        float dx = a.x - bq.x, dy = a.y - bq.y, dz = a.z - bq.z, dw = a.w - bq.w;
        acc += dx * dx + dy * dy + dz * dz + dw * dw;
    }
#pragma unroll
    for (int o = 4; o > 0; o >>= 1) acc += __shfl_down_sync(0xffffffffu, acc, o, 8);

    bool valid = false;
    int nr = -1, nc = -1;
    if (lane8 < 2) {
        nr = g_new_idx[r];
        nc = g_new_idx[c];
        valid = (nr >= 0) && (nc >= 0);
    }

    if (lane8 == 0) {
        float S = expf(acc > 0.0f ? sqrtf(acc) : 0.0f);   // _safe_norm semantics
        g_S[e] = S;
        atomicAdd(&g_hist1[__float_as_uint(S) >> 16], 1u);
        out[OFF_EIDX + e]      = (float)(valid ? nr : -1);
        out[OFF_EIDX + NE + e] = (float)(valid ? nc : -1);
    }
    if (lane8 < 2) {
        float4 a = valid ? ((const float4*)eattr)[(size_t)e * 2 + lane8]
                         : make_float4(0.f, 0.f, 0.f, 0.f);
        ((float4*)(out + OFF_EATTR))[(size_t)e * 2 + lane8] = a;
    }
}

// ---- hierarchical k-th locate in a 65536-bin histogram (one 1024-thr block) -
// mode 0: write g_sel_hi = bin, g_rem = remainder
// mode 1: write g_th = bits((g_sel_hi<<16) | bin)
__device__ __forceinline__ void find_kth_65536(const unsigned* __restrict__ hist,
                                               unsigned k, int mode) {
    __shared__ unsigned csum[64];
    __shared__ unsigned cpre[64];
    __shared__ int      sel_chunk;
    __shared__ unsigned rem_s;
    __shared__ unsigned warpsum[32];

    const int t = threadIdx.x;
    const int lane = t & 31, w = t >> 5;

    // stage A: 64 chunk sums (1024 bins each); warp w handles chunks 2w, 2w+1.
    #pragma unroll
    for (int cc = 0; cc < 2; cc++) {
        int c = w * 2 + cc;
        unsigned s = 0;
        #pragma unroll
        for (int i = lane; i < 1024; i += 32) s += hist[c * 1024 + i];  // coalesced
        #pragma unroll
        for (int o = 16; o > 0; o >>= 1) s += __shfl_down_sync(~0u, s, o);
        if (lane == 0) csum[c] = s;
    }
    __syncthreads();

    // stage B: parallel exclusive prefix over 64 chunk sums, pick chunk.
    if (t < 64) {
        unsigned s = 0;
        for (int i = 0; i < t; i++) s += csum[i];     // independent smem loads
        cpre[t] = s;
    }
    __syncthreads();
    if (t < 64) {
        if (k >= cpre[t] && k < cpre[t] + csum[t]) { sel_chunk = t; rem_s = k - cpre[t]; }
    }
    __syncthreads();

    // stage C: coalesced block scan of the selected chunk's 1024 bins.
    const int C = sel_chunk;
    const unsigned kk = rem_s;
    unsigned h = hist[C * 1024 + t];

    // block exclusive scan of h
    unsigned incl = h;
    #pragma unroll
    for (int o = 1; o < 32; o <<= 1) {
        unsigned n = __shfl_up_sync(~0u, incl, o);
        if (lane >= o) incl += n;
    }
    if (lane == 31) warpsum[w] = incl;
    __syncthreads();
    if (w == 0) {
        unsigned ws = warpsum[lane];
        #pragma unroll
        for (int o = 1; o < 32; o <<= 1) {
            unsigned n = __shfl_up_sync(~0u, ws, o);
            if (lane >= o) ws += n;
        }
        warpsum[lane] = ws;  // inclusive warp totals
    }
    __syncthreads();
    unsigned pre = ((w == 0) ? 0u : warpsum[w - 1]) + incl - h;   // exclusive

    if (kk >= pre && kk < pre + h) {
        unsigned bin = (unsigned)(C * 1024 + t);
        if (mode == 0) { g_sel_hi = bin; g_rem = kk - pre; }
        else           { g_th = __uint_as_float((g_sel_hi << 16) | bin); }
    }
}

__global__ void scan1_kernel() { find_kth_65536(g_hist1, K0, 0); }

// ---- histogram of low-16 bits within the selected high-16 bucket -----------
__global__ void hist2_kernel() {
    int e = blockIdx.x * blockDim.x + threadIdx.x;
    if (e >= NE) return;
    unsigned b = __float_as_uint(g_S[e]);
    if ((b >> 16) == g_sel_hi) atomicAdd(&g_hist2[b & 0xffffu], 1u);
}

__global__ void scan2_kernel() { find_kth_65536(g_hist2, g_rem, 1); }

// ---- final select mask -----------------------------------------------------
__global__ void select_kernel(float* __restrict__ out) {
    int e = blockIdx.x * blockDim.x + threadIdx.x;
    if (e >= NE) return;
    out[OFF_SEL + e] = (g_S[e] > g_th) ? 1.0f : 0.0f;
}

extern "C" void kernel_launch(void* const* d_in, const int* in_sizes, int n_in,
                              void* d_out, int out_size) {
    const float* x     = (const float*)d_in[0];
    const float* score = (const float*)d_in[1];
    const int*   ei    = (const int*)d_in[2];
    const float* eattr = (const float*)d_in[3];
    float* out = (float*)d_out;

    topk_kernel<<<BGRAPH, 1024>>>(score, out);
    gather_x_kernel<<<(PSEL * 16 + 255) / 256, 256>>>(x, out);
    edge_kernel<<<(NE * 8) / 256, 256>>>(ei, x, eattr, out);
    scan1_kernel<<<1, 1024>>>();
    hist2_kernel<<<NE / 256, 256>>>();
    scan2_kernel<<<1, 1024>>>();
    select_kernel<<<NE / 256, 256>>>(out);
}

// round 10
// speedup vs baseline: 1.3706x; 1.0024x over previous
#include <cuda_runtime.h>

// ---- problem constants -----------------------------------------------------
#define BGRAPH 64
#define N_PER  2048
#define FDIM   64
#define NE     1048576
#define NNODE  (BGRAPH * N_PER)      // 131072
#define KSEL   1639                   // ceil(0.8*2048)
#define PSEL   (BGRAPH * KSEL)        // 104896
#define K0     209715                 // ascending rank of threshold: E-1 - int(0.8*(E-1))

// ---- output layout (float32, concatenated in return order) -----------------
#define OFF_X      0
#define OFF_EIDX   6713344            // PSEL*FDIM
#define OFF_EATTR  8810496            // + 2*NE
#define OFF_BATCH  17199104           // + 8*NE
#define OFF_SEL    17304000           // + PSEL

// ---- device scratch (no allocation allowed) --------------------------------
__device__ float        g_S[NE];
__device__ int          g_new_idx[NNODE];
__device__ int          g_perm[PSEL];
__device__ unsigned int g_hist1[65536];
__device__ unsigned int g_hist2[65536];
__device__ unsigned int g_sel_hi;
__device__ unsigned int g_rem;
__device__ float        g_th;

// ---- per-graph top-k via bitonic sort of packed (desc score, asc idx) keys -
// Also zeroes both radix histograms (64 blocks x 1024 threads = 65536 entries).
__global__ void topk_kernel(const float* __restrict__ score) {
    __shared__ unsigned long long keys[N_PER];
    const int b = blockIdx.x;
    const int t = threadIdx.x;           // 1024 threads

    {   // zero histograms: global thread id covers [0, 65536)
        int h = b * 1024 + t;
        g_hist1[h] = 0u;
        g_hist2[h] = 0u;
    }

    for (int i = t; i < N_PER; i += 1024) {
        float s = score[b * N_PER + i];
        unsigned int bits = __float_as_uint(s);
        bits = (bits & 0x80000000u) ? ~bits : (bits | 0x80000000u);  // float->asc uint
        unsigned int dk = ~bits;                                      // descending key
        keys[i] = (((unsigned long long)dk) << 32) | (unsigned int)i;
        g_new_idx[b * N_PER + i] = -1;
    }
    __syncthreads();

    // bitonic sort ascending on u64 => descending score, lower index first on ties
    for (int k = 2; k <= N_PER; k <<= 1) {
        for (int j = k >> 1; j > 0; j >>= 1) {
            for (int i = t; i < N_PER; i += 1024) {
                int ixj = i ^ j;
                if (ixj > i) {
                    unsigned long long a = keys[i], c = keys[ixj];
                    bool up = ((i & k) == 0);
                    if ((a > c) == up) { keys[i] = c; keys[ixj] = a; }
                }
            }
            __syncthreads();
        }
    }

    for (int i = t; i < KSEL; i += 1024) {
        int idx  = (int)(keys[i] & 0xffffffffu);
        int node = b * N_PER + idx;
        int newp = b * KSEL + i;
        g_new_idx[node] = newp;
        g_perm[newp]    = node;
    }
}

// ---- x_out gather: one float4 per thread -----------------------------------
__global__ void gather_x_kernel(const float* __restrict__ x, float* __restrict__ out) {
    int tid = blockIdx.x * blockDim.x + threadIdx.x;   // PSEL*16 threads
    if (tid >= PSEL * 16) return;
    int row = tid >> 4, c = tid & 15;
    int node = g_perm[row];
    float4 v = ((const float4*)x)[(size_t)node * 16 + c];
    ((float4*)(out + OFF_X))[(size_t)row * 16 + c] = v;
}

// ---- batch_out: pure function of index, no deps -----------------------------
__global__ void batch_kernel(float* __restrict__ out) {
    int p = blockIdx.x * blockDim.x + threadIdx.x;
    if (p >= PSEL) return;
    out[OFF_BATCH + p] = (float)((unsigned)p / (unsigned)KSEL);
}

// ---- edge kernel: 8 threads per edge (stream launch index 3 -> profiled) ---
__global__ void edge_kernel(const int* __restrict__ ei,
                            const float* __restrict__ x,
                            const float* __restrict__ eattr,
                            float* __restrict__ out) {
    int g = blockIdx.x * blockDim.x + threadIdx.x;
    int e = g >> 3, lane8 = g & 7;
    if (e >= NE) return;

    int r = ei[e], c = ei[NE + e];

    const float4* xr = (const float4*)(x + (size_t)r * FDIM);
    const float4* xc = (const float4*)(x + (size_t)c * FDIM);
    float acc = 0.0f;
#pragma unroll
    for (int j = lane8; j < 16; j += 8) {
        float4 a = xr[j], bq = xc[j];
        float dx = a.x - bq.x, dy = a.y - bq.y, dz = a.z - bq.z, dw = a.w - bq.w;
        acc += dx * dx + dy * dy + dz * dz + dw * dw;
    }
#pragma unroll
    for (int o = 4; o > 0; o >>= 1) acc += __shfl_down_sync(0xffffffffu, acc, o, 8);

    bool valid = false;
    int nr = -1, nc = -1;
    if (lane8 < 2) {
        nr = g_new_idx[r];
        nc = g_new_idx[c];
        valid = (nr >= 0) && (nc >= 0);
    }

    if (lane8 == 0) {
        float S = expf(acc > 0.0f ? sqrtf(acc) : 0.0f);   // _safe_norm semantics
        g_S[e] = S;
        atomicAdd(&g_hist1[__float_as_uint(S) >> 16], 1u);
        out[OFF_EIDX + e]      = (float)(valid ? nr : -1);
        out[OFF_EIDX + NE + e] = (float)(valid ? nc : -1);
    }
    if (lane8 < 2) {
        float4 a = valid ? ((const float4*)eattr)[(size_t)e * 2 + lane8]
                         : make_float4(0.f, 0.f, 0.f, 0.f);
        ((float4*)(out + OFF_EATTR))[(size_t)e * 2 + lane8] = a;
    }
}

// ---- hierarchical k-th locate in a 65536-bin histogram (one 1024-thr block) -
// mode 0: write g_sel_hi = bin, g_rem = remainder
// mode 1: write g_th = bits((g_sel_hi<<16) | bin)
__device__ __forceinline__ void find_kth_65536(const unsigned* __restrict__ hist,
                                               unsigned k, int mode) {
    __shared__ unsigned csum[64];
    __shared__ unsigned cpre[64];
    __shared__ int      sel_chunk;
    __shared__ unsigned rem_s;
    __shared__ unsigned warpsum[32];

    const int t = threadIdx.x;
    const int lane = t & 31, w = t >> 5;

    // stage A: 64 chunk sums (1024 bins each) with uint4 loads for 4x MLP.
    const uint4* h4 = (const uint4*)hist;
    #pragma unroll
    for (int cc = 0; cc < 2; cc++) {
        int c = w * 2 + cc;
        unsigned s = 0;
        #pragma unroll
        for (int i = lane; i < 256; i += 32) {          // 256 uint4 per chunk
            uint4 v = h4[c * 256 + i];
            s += v.x + v.y + v.z + v.w;
        }
        #pragma unroll
        for (int o = 16; o > 0; o >>= 1) s += __shfl_down_sync(~0u, s, o);
        if (lane == 0) csum[c] = s;
    }
    __syncthreads();

    // stage B: parallel exclusive prefix over 64 chunk sums, pick chunk.
    if (t < 64) {
        unsigned s = 0;
        for (int i = 0; i < t; i++) s += csum[i];
        cpre[t] = s;
    }
    __syncthreads();
    if (t < 64) {
        if (k >= cpre[t] && k < cpre[t] + csum[t]) { sel_chunk = t; rem_s = k - cpre[t]; }
    }
    __syncthreads();

    // stage C: coalesced block scan of the selected chunk's 1024 bins.
    const int C = sel_chunk;
    const unsigned kk = rem_s;
    unsigned h = hist[C * 1024 + t];

    unsigned incl = h;
    #pragma unroll
    for (int o = 1; o < 32; o <<= 1) {
        unsigned n = __shfl_up_sync(~0u, incl, o);
        if (lane >= o) incl += n;
    }
    if (lane == 31) warpsum[w] = incl;
    __syncthreads();
    if (w == 0) {
        unsigned ws = warpsum[lane];
        #pragma unroll
        for (int o = 1; o < 32; o <<= 1) {
            unsigned n = __shfl_up_sync(~0u, ws, o);
            if (lane >= o) ws += n;
        }
        warpsum[lane] = ws;
    }
    __syncthreads();
    unsigned pre = ((w == 0) ? 0u : warpsum[w - 1]) + incl - h;   // exclusive

    if (kk >= pre && kk < pre + h) {
        unsigned bin = (unsigned)(C * 1024 + t);
        if (mode == 0) { g_sel_hi = bin; g_rem = kk - pre; }
        else           { g_th = __uint_as_float((g_sel_hi << 16) | bin); }
    }
}

__global__ void scan1_kernel() { find_kth_65536(g_hist1, K0, 0); }

// ---- histogram of low-16 bits within the selected high-16 bucket -----------
__global__ void hist2_kernel() {
    int e = blockIdx.x * blockDim.x + threadIdx.x;
    if (e >= NE) return;
    unsigned b = __float_as_uint(g_S[e]);
    if ((b >> 16) == g_sel_hi) atomicAdd(&g_hist2[b & 0xffffu], 1u);
}

__global__ void scan2_kernel() { find_kth_65536(g_hist2, g_rem, 1); }

// ---- final select mask -----------------------------------------------------
__global__ void select_kernel(float* __restrict__ out) {
    int e = blockIdx.x * blockDim.x + threadIdx.x;
    if (e >= NE) return;
    out[OFF_SEL + e] = (g_S[e] > g_th) ? 1.0f : 0.0f;
}

extern "C" void kernel_launch(void* const* d_in, const int* in_sizes, int n_in,
                              void* d_out, int out_size) {
    const float* x     = (const float*)d_in[0];
    const float* score = (const float*)d_in[1];
    const int*   ei    = (const int*)d_in[2];
    const float* eattr = (const float*)d_in[3];
    float* out = (float*)d_out;

    topk_kernel<<<BGRAPH, 1024>>>(score);                       // idx 0
    gather_x_kernel<<<(PSEL * 16 + 255) / 256, 256>>>(x, out);  // idx 1
    batch_kernel<<<(PSEL + 255) / 256, 256>>>(out);             // idx 2
    edge_kernel<<<(NE * 8) / 256, 256>>>(ei, x, eattr, out);    // idx 3 (profiled)
    scan1_kernel<<<1, 1024>>>();                                // idx 4
    hist2_kernel<<<NE / 256, 256>>>();                          // idx 5
    scan2_kernel<<<1, 1024>>>();                                // idx 6
    select_kernel<<<NE / 256, 256>>>(out);                      // idx 7
}